// round 17
// baseline (speedup 1.0000x reference)
#include <cuda_runtime.h>
#include <cuda_bf16.h>
#include <cstdint>
#include <cstddef>

#define LOG2E 1.4426950408889634f
#define LN2   0.6931471805599453f

// ---- static scratch ----
// cost in diag layout [b][i+j][j], log2e-scaled, padded for deep branchless prefetch
__device__ float g_cost[64 * 512 * 256 + 4096];

__device__ __forceinline__ float ex2f(float x) {
    float y; asm("ex2.approx.f32 %0, %1;" : "=f"(y) : "f"(x)); return y;
}
__device__ __forceinline__ float lg2f(float x) {
    float y; asm("lg2.approx.f32 %0, %1;" : "=f"(y) : "f"(x)); return y;
}
__device__ __forceinline__ uint32_t sptr(const void* p) {
    return (uint32_t)__cvta_generic_to_shared(p);
}
// stable soft-min of 3 in log2 domain
__device__ __forceinline__ float sm3(float a, float b, float c) {
    float mn = fminf(a, b), mx = fmaxf(a, b);
    float lo  = fminf(mn, c);
    float mid = fmaxf(mn, fminf(mx, c));
    float hi  = fmaxf(mx, c);
    return lo - lg2f(1.0f + ex2f(lo - mid) + ex2f(lo - hi));
}

// ================= K1: fused norms + bf16 mma cost GEMM =================
// 256 blocks = 64 batches x (2x2 tiles of 128x128). 8 warps, warp tile 32(m) x 64(n).
__global__ void __launch_bounds__(256) cost_gemm_kernel(const float* __restrict__ X,
                                                        const float* __restrict__ Y,
                                                        float* __restrict__ out) {
    __shared__ __align__(16) char smraw[33280];
    unsigned short* Xs = (unsigned short*)smraw;       // [128][64] bf16, swizzled
    unsigned short* Ys = Xs + 128 * 64;
    float* Cs = (float*)smraw;                          // [64][130] (aliases Xs/Ys)
    __shared__ float xnorm[128], ynorm[128];            // log2e * |row|^2 (local tile idx)

    int bx = blockIdx.x;
    int b = bx >> 2, tm = (bx >> 1) & 1, tn = bx & 1;
    int t = threadIdx.x, lane = t & 31, w = t >> 5;
    int wr = w >> 1, wc = w & 1;

    if (bx == 0 && t == 0) out[0] = 0.f;

    const float* Xg = X + (size_t)(b * 256 + tm * 128) * 128;
    const float* Yg = Y + (size_t)(b * 256 + tn * 128) * 128;

    float acc[2][8][4];
#pragma unroll
    for (int am = 0; am < 2; am++)
#pragma unroll
        for (int bn = 0; bn < 8; bn++)
#pragma unroll
            for (int k = 0; k < 4; k++) acc[am][bn][k] = 0.f;

    float rsx[8], rsy[8];
#pragma unroll
    for (int p = 0; p < 8; p++) { rsx[p] = 0.f; rsy[p] = 0.f; }

    int arow0 = 32 * wr + (lane & 15);
    int ahalf = lane >> 4;
    int brow0 = 64 * wc + (lane & 7) + ((lane >> 4) << 3);
    int bhalf = (lane >> 3) & 1;

    int lrow = t >> 4;     // base row (0..15); rows covered: lrow + 16p
    int c4 = t & 15;       // float4 slot within 64-col chunk

    for (int kc = 0; kc < 128; kc += 64) {
        __syncthreads();
#pragma unroll
        for (int p = 0; p < 8; p++) {
            int row = lrow + 16 * p;
            float4 f = *(const float4*)(Xg + (size_t)row * 128 + kc + c4 * 4);
            rsx[p] = fmaf(f.x, f.x, fmaf(f.y, f.y, fmaf(f.z, f.z, fmaf(f.w, f.w, rsx[p]))));
            ushort4 u;
            u.x = __bfloat16_as_ushort(__float2bfloat16(f.x));
            u.y = __bfloat16_as_ushort(__float2bfloat16(f.y));
            u.z = __bfloat16_as_ushort(__float2bfloat16(f.z));
            u.w = __bfloat16_as_ushort(__float2bfloat16(f.w));
            int soff = row * 128 + (((c4 >> 1) ^ (row & 7)) << 4) + (c4 & 1) * 8;
            *(ushort4*)((char*)Xs + soff) = u;
        }
#pragma unroll
        for (int p = 0; p < 8; p++) {
            int row = lrow + 16 * p;
            float4 f = *(const float4*)(Yg + (size_t)row * 128 + kc + c4 * 4);
            rsy[p] = fmaf(f.x, f.x, fmaf(f.y, f.y, fmaf(f.z, f.z, fmaf(f.w, f.w, rsy[p]))));
            ushort4 u;
            u.x = __bfloat16_as_ushort(__float2bfloat16(f.x));
            u.y = __bfloat16_as_ushort(__float2bfloat16(f.y));
            u.z = __bfloat16_as_ushort(__float2bfloat16(f.z));
            u.w = __bfloat16_as_ushort(__float2bfloat16(f.w));
            int soff = row * 128 + (((c4 >> 1) ^ (row & 7)) << 4) + (c4 & 1) * 8;
            *(ushort4*)((char*)Ys + soff) = u;
        }
        __syncthreads();
#pragma unroll
        for (int ks = 0; ks < 4; ks++) {
            uint32_t a[2][4], bf[8][2];
#pragma unroll
            for (int am = 0; am < 2; am++) {
                int row = arow0 + 16 * am;
                int kb16 = ks * 2 + ahalf;
                uint32_t ad = sptr((char*)Xs + row * 128 + ((kb16 ^ (row & 7)) << 4));
                asm volatile("ldmatrix.sync.aligned.m8n8.x4.shared.b16 {%0,%1,%2,%3},[%4];"
                    : "=r"(a[am][0]), "=r"(a[am][1]), "=r"(a[am][2]), "=r"(a[am][3]) : "r"(ad));
            }
#pragma unroll
            for (int bp = 0; bp < 4; bp++) {
                int row = brow0 + 16 * bp;
                int kb16 = ks * 2 + bhalf;
                uint32_t ad = sptr((char*)Ys + row * 128 + ((kb16 ^ (row & 7)) << 4));
                asm volatile("ldmatrix.sync.aligned.m8n8.x4.shared.b16 {%0,%1,%2,%3},[%4];"
                    : "=r"(bf[2 * bp][0]), "=r"(bf[2 * bp][1]),
                      "=r"(bf[2 * bp + 1][0]), "=r"(bf[2 * bp + 1][1]) : "r"(ad));
            }
#pragma unroll
            for (int am = 0; am < 2; am++)
#pragma unroll
                for (int bn = 0; bn < 8; bn++)
                    asm volatile("mma.sync.aligned.m16n8k16.row.col.f32.bf16.bf16.f32 "
                        "{%0,%1,%2,%3},{%4,%5,%6,%7},{%8,%9},{%0,%1,%2,%3};"
                        : "+f"(acc[am][bn][0]), "+f"(acc[am][bn][1]),
                          "+f"(acc[am][bn][2]), "+f"(acc[am][bn][3])
                        : "r"(a[am][0]), "r"(a[am][1]), "r"(a[am][2]), "r"(a[am][3]),
                          "r"(bf[bn][0]), "r"(bf[bn][1]));
        }
    }

    // norm reduction: width-16 shfl, single writer per row (deterministic)
#pragma unroll
    for (int p = 0; p < 8; p++) {
        float sx = rsx[p], sy = rsy[p];
#pragma unroll
        for (int off = 8; off >= 1; off >>= 1) {
            sx += __shfl_xor_sync(0xffffffffu, sx, off, 16);
            sy += __shfl_xor_sync(0xffffffffu, sy, off, 16);
        }
        if ((t & 15) == 0) {
            xnorm[lrow + 16 * p] = sx * LOG2E;
            ynorm[lrow + 16 * p] = sy * LOG2E;
        }
    }

    // epilogue: stage to smem in 2 row-halves, then coalesced diag-major stores
    __syncthreads();
    float* cb = g_cost + (size_t)b * 512 * 256;

#pragma unroll
    for (int h = 0; h < 2; h++) {
        if ((wr >> 1) == h) {
            int rbase = 32 * (wr & 1);
#pragma unroll
            for (int am = 0; am < 2; am++)
#pragma unroll
                for (int bn = 0; bn < 8; bn++) {
                    int rr = rbase + 16 * am + (lane >> 2);
                    int cc = 64 * wc + 8 * bn + 2 * (lane & 3);
                    *(float2*)&Cs[rr * 130 + cc] = make_float2(acc[am][bn][0], acc[am][bn][1]);
                    *(float2*)&Cs[(rr + 8) * 130 + cc] = make_float2(acc[am][bn][2], acc[am][bn][3]);
                }
        }
        __syncthreads();
        int tt = t & 127;
        for (int s2 = 0; s2 < 192; s2 += 2) {
            int s = s2 + (t >> 7);                 // local diag within half: 0..191
            int lj_lo = max(0, s - 63), lj_hi = min(127, s);
            int lj = lj_lo + tt;
            if (s < 191 && lj <= lj_hi) {
                int li = s - lj;
                int i = tm * 128 + 64 * h + li;
                int j = tn * 128 + lj;
                float v = xnorm[64 * h + li] + ynorm[lj] - (2.0f * LOG2E) * Cs[li * 130 + lj];
                cb[(size_t)(i + j) * 256 + j] = v;
            }
        }
        __syncthreads();
    }
}

// ================= K2: 4-diag-per-barrier wavefront soft-DTW =================
// 64 blocks (1/batch) x 128 threads (4 warps). Thread t owns cols jA=2t+1, jB=2t+2.
// Lanes 0-3 of each warp redundantly maintain a 4-column ghost block (cols 64w-3..64w,
// exact state re-imported from the left warp's lanes 30/31 every iteration), which
// bridges the cross-warp gap for 4 diagonals per __syncthreads (128 barriers total).
// Cost: depth-2-iteration register ring (8 rows) + 1-iteration-ahead ghost-cost prefetch.
__global__ void __launch_bounds__(128) dp_kernel(float* __restrict__ out) {
    __shared__ float4 bndP[2][5][2];   // [parity][consumer warp][slot]; slot0=lane30, slot1=lane31

    int t = threadIdx.x, lane = t & 31, w = t >> 5, b = blockIdx.x;
    const float INF = __int_as_float(0x7f800000);
    const float* cost  = g_cost + (size_t)b * 512 * 256;
    const float* costT = cost + 2 * t;                    // own cells (jA-1 = 2t)
    int gofs = (w > 0) ? (64 * w - 4) : 0;                // ghost j-1 base (clamped for w=0)
    const float* costG = cost + gofs + lane;              // lanes 0..3 meaningful

    if (t < 20) ((float4*)bndP)[t] = make_float4(INF, INF, INF, INF);
    __syncthreads();

    float r1A = INF, r2A = INF, r1B = INF, r2B = INF;
    float G1 = INF, G2 = INF;     // ghost col state (lane c<4: col 64w-3+c)

    float2 ec[4][4];              // [ring slot][s]; slot k&3 feeds iter k
#pragma unroll
    for (int i = 0; i < 2; i++)
#pragma unroll
        for (int s = 0; s < 4; s++)
            ec[i][s] = *(const float2*)(costT + (size_t)(4 * i + s) * 256);
    float gq[4], gqn[4];
#pragma unroll
    for (int s = 0; s < 4; s++) gq[s] = costG[(size_t)s * 256];

    int jA = 2 * t + 1;
    int jG = 64 * w - 3 + lane;   // ghost col (lanes 0..3)
    bool p0 = (t == 0), isL0 = (lane == 0);

#pragma unroll 4
    for (int k = 0; k < 128; ++k) {
        int d0 = 4 * k + 2;
        int par = k & 1;

        // prefetch: main rows for iter k+2, ghost rows for iter k+1
#pragma unroll
        for (int s = 0; s < 4; s++)
            ec[(k + 2) & 3][s] = *(const float2*)(costT + (size_t)(4 * k + 8 + s) * 256);
#pragma unroll
        for (int s = 0; s < 4; s++)
            gqn[s] = costG[(size_t)(4 * k + 4 + s) * 256];

        // import exact ghost state (lanes 0..3; junk for others, never consumed)
        {
            float4 q = bndP[par][w][(lane >> 1) & 1];
            G1 = (lane & 1) ? q.z : q.x;
            G2 = (lane & 1) ? q.w : q.y;
        }
        float pd = __shfl_up_sync(0xffffffffu, r2B, 1);   // R[d0-2][jB_left]

#pragma unroll
        for (int s = 0; s < 4; s++) {
            int d = d0 + s;
            float sh1 = __shfl_up_sync(0xffffffffu, r1B, 1);    // R[d-1][jB_left]
            float g31 = __shfl_sync(0xffffffffu, G1, 3);        // R[d-1][64w]
            float g32 = __shfl_sync(0xffffffffu, G2, 3);        // R[d-2][64w]
            float leftA = isL0 ? g31 : sh1;
            float diagA = isL0 ? g32 : pd;
            if (p0) { leftA = INF; diagA = (k == 0 && s == 0) ? 0.0f : INF; }

            float rdA = ec[k & 3][s].x + sm3(r1A, leftA, diagA);
            float rdB = ec[k & 3][s].y + sm3(r1B, r1A, r2A);

            // ghost update (lane-parallel; lane c uses lane c-1's pre-commit state)
            float gu1 = __shfl_up_sync(0xffffffffu, G1, 1);
            float gu2 = __shfl_up_sync(0xffffffffu, G2, 1);
            if (isL0) { gu1 = INF; gu2 = INF; }   // col left of ghost block: invalid cell
            float gn = gq[s] + sm3(G1, gu1, gu2);

            // commit (r2 <- old r1 always; r1 <- new if cell active)
            unsigned iA = (unsigned)(d - jA);
            r2A = r1A; if ((iA - 1u) < 256u) r1A = rdA;
            r2B = r1B; if ((iA - 2u) < 256u) r1B = rdB;
            unsigned ig = (unsigned)(d - jG);
            G2 = G1;   if ((ig - 1u) < 256u) G1 = gn;
            pd = sh1;
        }

        // publish exact boundary state for the right warp's next iteration
        if (lane >= 30) bndP[par ^ 1][w + 1][lane - 30] = make_float4(r1A, r2A, r1B, r2B);
        __syncthreads();

#pragma unroll
        for (int s = 0; s < 4; s++) gq[s] = gqn[s];
    }

    // t=127 col jB=256: r1B = R[512][256] (computed at k=127, s=2; s=3 guarded off)
    if (t == 127) atomicAdd(out, r1B * (LN2 / 64.0f));
}

extern "C" void kernel_launch(void* const* d_in, const int* in_sizes, int n_in,
                              void* d_out, int out_size) {
    const float* x = (const float*)d_in[0];
    const float* y = (const float*)d_in[1];
    float* out = (float*)d_out;
    cost_gemm_kernel<<<256, 256>>>(x, y, out);
    dp_kernel<<<64, 128>>>(out);
}